// round 1
// baseline (speedup 1.0000x reference)
#include <cuda_runtime.h>
#include <cuda_bf16.h>
#include <stdint.h>

// Problem constants (match reference)
#define NSEG   8
#define KPTS   768
#define NPTS   10
#define NMAPS  7            // NSEG - SEG_DIST
#define WIMG   1024
#define KK     (KPTS * KPTS)          // 589824
#define STOT   (NMAPS * KK)           // 4128768  (length of each of the 4 output rows)
#define PLANE  (WIMG * WIMG)          // 1048576

// Scratch: PAF transposed to channel-interleaved (m, y, x, {c0,c1}) so one 8B
// load fetches both channels of a sample point (halves L2 sector traffic).
__device__ float2 g_pafi[NMAPS * PLANE];   // 56 MB static device scratch (allowed)

__global__ void transpose_paf_kernel(const float* __restrict__ paf) {
    int idx = blockIdx.x * blockDim.x + threadIdx.x;   // over NMAPS*PLANE
    if (idx >= NMAPS * PLANE) return;
    int m = idx / PLANE;
    int r = idx - m * PLANE;
    const float* base = paf + (size_t)m * 2 * PLANE;
    float c0 = __ldg(base + r);
    float c1 = __ldg(base + PLANE + r);
    g_pafi[idx] = make_float2(c0, c1);
}

__global__ void __launch_bounds__(256) paf_weight_kernel(
    const int* __restrict__ sk,      // skeletons: (NSEG*KPTS, 3) int32 [seg, x, y]
    float* __restrict__ out)         // [i1 | i2 | li | R], each STOT floats
{
    int idx = blockIdx.x * blockDim.x + threadIdx.x;
    if (idx >= STOT) return;

    // idx = m*KK + i*KPTS + j ; j = p1 index (lane-fast), i = p2 index, m = map
    int j = idx % KPTS;
    int t = idx / KPTS;
    int i = t % KPTS;
    int m = t / KPTS;

    // p1 = segment m, point j ; p2 = segment m+1, point i (warp-uniform-ish)
    int b1 = (m * KPTS + j) * 3;
    int b2 = ((m + 1) * KPTS + i) * 3;
    int x1 = __ldg(sk + b1 + 1);
    int y1 = __ldg(sk + b1 + 2);
    int x2 = __ldg(sk + b2 + 1);
    int y2 = __ldg(sk + b2 + 2);

    const float2* __restrict__ pafm = g_pafi + (size_t)m * PLANE;

    float s0 = 0.f, s1 = 0.f;
#pragma unroll
    for (int p = 0; p < NPTS; p++) {
        // integer floor-div by (NPTS-1)=9; operands nonnegative so C '/' == floor
        int lx = (x1 * (NPTS - 1 - p) + x2 * p) / (NPTS - 1);
        int ly = (y1 * (NPTS - 1 - p) + y2 * p) / (NPTS - 1);
        float2 v = __ldg(&pafm[ly * WIMG + lx]);
        s0 += v.x;
        s1 += v.y;
    }

    float dx = (float)(x2 - x1);
    float dy = (float)(y2 - y1);
    float R2 = dx * dx + dy * dy;
    float R  = sqrtf(R2);
    // li = mean_p sum_c (tv_c/R)*paf_c = (dx*s0 + dy*s1) / (R*NPTS); NaN (R==0) -> 0
    float li = (R2 > 0.f) ? (dx * s0 + dy * s1) / (R * (float)NPTS) : 0.f;

    out[idx]            = (float)(m * KPTS + j);         // edges_indices[0]
    out[STOT + idx]     = (float)((m + 1) * KPTS + i);   // edges_indices[1]
    out[2 * STOT + idx] = li;                            // edges_costs[0]
    out[3 * STOT + idx] = R;                             // edges_costs[1]
}

extern "C" void kernel_launch(void* const* d_in, const int* in_sizes, int n_in,
                              void* d_out, int out_size) {
    const int*   sk  = (const int*)d_in[0];     // skeletons (6144, 3) int32
    const float* paf = (const float*)d_in[1];   // PAF (7, 2, 1024, 1024) float32
    float* out = (float*)d_out;

    {
        int n = NMAPS * PLANE;
        transpose_paf_kernel<<<(n + 255) / 256, 256>>>(paf);
    }
    {
        int n = STOT;
        paf_weight_kernel<<<(n + 255) / 256, 256>>>(sk, out);
    }
}

// round 2
// speedup vs baseline: 1.1075x; 1.1075x over previous
#include <cuda_runtime.h>
#include <cuda_bf16.h>
#include <stdint.h>

// Problem constants (match reference)
#define NSEG   8
#define KPTS   768
#define NPTS   10
#define NMAPS  7            // NSEG - SEG_DIST
#define WIMG   1024
#define KK     (KPTS * KPTS)          // 589824
#define STOT   (NMAPS * KK)           // 4128768  (length of each of the 4 output rows)
#define PLANE  (WIMG * WIMG)          // 1048576

// PAF transposed to channel-interleaved (m, y, x, {c0,c1}): one 8B load fetches
// both channels of a sample point (halves scattered L1tex wavefronts).
__device__ float2 g_pafi[NMAPS * PLANE];     // 56 MB static scratch

// Endpoint samples: E0[m*KPTS+j] = PAF at p1 (sample p=0), E9[m*KPTS+i] = PAF at p2
// (sample p=9). These depend on only one endpoint, so hoisting them removes one
// scattered gather per pair (it was redone 768x across the other endpoint).
__device__ float2 g_e0[NMAPS * KPTS];
__device__ float2 g_e9[NMAPS * KPTS];

// ---------------------------------------------------------------------------
// Transpose: (m, c, y, x) -> (m, y, x, {c0,c1}), 4 pixels per thread (float4).
__global__ void __launch_bounds__(256) transpose_paf_kernel(const float* __restrict__ paf) {
    int idx4 = blockIdx.x * blockDim.x + threadIdx.x;        // over NMAPS*PLANE/4
    if (idx4 >= NMAPS * (PLANE / 4)) return;
    int m  = idx4 / (PLANE / 4);
    int r4 = idx4 - m * (PLANE / 4);
    const float4* c0p = (const float4*)(paf + (size_t)m * 2 * PLANE);
    const float4* c1p = (const float4*)(paf + (size_t)m * 2 * PLANE + PLANE);
    float4 c0 = __ldg(c0p + r4);
    float4 c1 = __ldg(c1p + r4);
    float4* dst = (float4*)&g_pafi[(size_t)m * PLANE + 4 * r4];
    dst[0] = make_float4(c0.x, c1.x, c0.y, c1.y);
    dst[1] = make_float4(c0.z, c1.z, c0.w, c1.w);
}

// ---------------------------------------------------------------------------
// Endpoint precompute: gathers from the ORIGINAL layout (no transpose dep).
__global__ void __launch_bounds__(256) endpoint_kernel(const int* __restrict__ sk,
                                                       const float* __restrict__ paf) {
    int t = blockIdx.x * blockDim.x + threadIdx.x;           // over 2*NMAPS*KPTS
    if (t >= 2 * NMAPS * KPTS) return;
    int which = t / (NMAPS * KPTS);                          // 0 -> E0, 1 -> E9
    int r = t - which * (NMAPS * KPTS);
    int m = r / KPTS;
    int q = r - m * KPTS;
    // E0 uses segment m point q; E9 uses segment m+1 point q
    int base = ((m + which) * KPTS + q) * 3;
    int x = __ldg(sk + base + 1);
    int y = __ldg(sk + base + 2);
    const float* pm = paf + (size_t)m * 2 * PLANE;
    float c0 = __ldg(pm + y * WIMG + x);
    float c1 = __ldg(pm + PLANE + y * WIMG + x);
    (which ? g_e9 : g_e0)[r] = make_float2(c0, c1);
}

// ---------------------------------------------------------------------------
__global__ void __launch_bounds__(256) paf_weight_kernel(
    const int* __restrict__ sk,      // skeletons: (NSEG*KPTS, 3) int32 [seg, x, y]
    float* __restrict__ out)         // [i1 | i2 | li | R], each STOT floats
{
    int idx = blockIdx.x * blockDim.x + threadIdx.x;
    if (idx >= STOT) return;

    // idx = m*KK + i*KPTS + j ; j = p1 index (lane-fast), i = p2 index, m = map
    int j = idx % KPTS;
    int t = idx / KPTS;
    int i = t % KPTS;
    int m = t / KPTS;

    int b1 = (m * KPTS + j) * 3;
    int b2 = ((m + 1) * KPTS + i) * 3;
    int x1 = __ldg(sk + b1 + 1);
    int y1 = __ldg(sk + b1 + 2);
    int x2 = __ldg(sk + b2 + 1);
    int y2 = __ldg(sk + b2 + 2);

    const float2* __restrict__ pafm = g_pafi + (size_t)m * PLANE;

    // Endpoint samples: coalesced (lane-fast j) and broadcast (uniform i) reads.
    float2 e0 = __ldg(&g_e0[m * KPTS + j]);
    float2 e9 = __ldg(&g_e9[m * KPTS + i]);
    float s0 = e0.x + e9.x;
    float s1 = e0.y + e9.y;

#pragma unroll
    for (int p = 1; p < NPTS - 1; p++) {
        // integer floor-div by 9; operands nonnegative so C '/' == floor
        int lx = (x1 * (NPTS - 1 - p) + x2 * p) / (NPTS - 1);
        int ly = (y1 * (NPTS - 1 - p) + y2 * p) / (NPTS - 1);
        float2 v = __ldg(&pafm[ly * WIMG + lx]);
        s0 += v.x;
        s1 += v.y;
    }

    float dx = (float)(x2 - x1);
    float dy = (float)(y2 - y1);
    float R2 = dx * dx + dy * dy;
    float R  = sqrtf(R2);
    // li = mean_p sum_c (tv_c/R)*paf_c = (dx*s0 + dy*s1) / (R*NPTS); NaN (R==0) -> 0
    float li = (R2 > 0.f) ? (dx * s0 + dy * s1) / (R * (float)NPTS) : 0.f;

    // Streaming stores: don't evict the L2-resident PAF with the 66MB output.
    __stcs(&out[idx],            (float)(m * KPTS + j));       // edges_indices[0]
    __stcs(&out[STOT + idx],     (float)((m + 1) * KPTS + i)); // edges_indices[1]
    __stcs(&out[2 * STOT + idx], li);                          // edges_costs[0]
    __stcs(&out[3 * STOT + idx], R);                           // edges_costs[1]
}

extern "C" void kernel_launch(void* const* d_in, const int* in_sizes, int n_in,
                              void* d_out, int out_size) {
    const int*   sk  = (const int*)d_in[0];     // skeletons (6144, 3) int32
    const float* paf = (const float*)d_in[1];   // PAF (7, 2, 1024, 1024) float32
    float* out = (float*)d_out;

    {
        int n = NMAPS * (PLANE / 4);
        transpose_paf_kernel<<<(n + 255) / 256, 256>>>(paf);
    }
    {
        int n = 2 * NMAPS * KPTS;
        endpoint_kernel<<<(n + 255) / 256, 256>>>(sk, paf);
    }
    {
        int n = STOT;
        paf_weight_kernel<<<(n + 255) / 256, 256>>>(sk, out);
    }
}